// round 7
// baseline (speedup 1.0000x reference)
#include <cuda_runtime.h>
#include <math.h>

// Problem constants
#define BQ 16
#define TQ 256
#define DQ 512
#define HQ 256
#define KQ 20
#define MR (BQ*TQ)          // 4096 rows
#define NB_DIR 64           // persistent blocks per LSTM direction

// ---------------- device scratch (no runtime allocation allowed) ----------------
__device__ float g_e [MR*DQ];        // embedding out / layer-0 input
__device__ float g_l0[MR*DQ];        // layer-0 bilstm output
__device__ float g_l1[MR*DQ];        // layer-1 bilstm output (residual source)
__device__ float g_t [MR*DQ];        // ff temp (relu)
__device__ float g_f [MR*DQ];        // ff temp
__device__ float g_ho[MR*HQ];        // ffo output
__device__ float g_xw[MR*2048];      // precomputed input-gate activations (both dirs)
__device__ float g_h [2][2][BQ][HQ]; // [dir][pingpong][batch][hidden]
__device__ unsigned g_flags[2][64];  // per-block step flags (dir-separated L2 lines)

// ---------------- packed f32x2 helpers (Blackwell FFMA2) ----------------
__device__ __forceinline__ unsigned long long ffma2(unsigned long long a,
                                                    unsigned long long b,
                                                    unsigned long long c) {
    unsigned long long d;
    asm("fma.rn.f32x2 %0, %1, %2, %3;" : "=l"(d) : "l"(a), "l"(b), "l"(c));
    return d;
}
__device__ __forceinline__ unsigned long long pk2(float x, float y) {
    unsigned long long r;
    asm("mov.b64 %0, {%1, %2};" : "=l"(r) : "f"(x), "f"(y));
    return r;
}
__device__ __forceinline__ float2 upk2(unsigned long long v) {
    float2 r;
    asm("mov.b64 {%0, %1}, %2;" : "=f"(r.x), "=f"(r.y) : "l"(v));
    return r;
}

// ---------------- fast activations (accurate to ~1e-6 rel) ----------------
__device__ __forceinline__ float sigf(float x) {
    return __fdividef(1.f, 1.f + __expf(-x));
}
__device__ __forceinline__ float tanh_fast(float x) {
    // tanh(x) = 1 - 2/(e^{2x}+1); saturates to +/-1 cleanly at overflow.
    return 1.f - __fdividef(2.f, __expf(2.f * x) + 1.f);
}

// ---------------- embedding gather ----------------
__global__ void k_embed(const int* __restrict__ x, const float* __restrict__ emb,
                        float* __restrict__ out)
{
    int row = blockIdx.x;                       // b*T + t
    int tok = x[row];
    const float4* src = (const float4*)(emb + (size_t)tok * DQ);
    float4*       dst = (float4*)(out + (size_t)row * DQ);
    for (int i = threadIdx.x; i < DQ/4; i += blockDim.x) dst[i] = src[i];
}

// ---------------- SGEMM: C[M,N] = A[M,K] * W[N,K]^T + bias (NT, fp32) ----------------
// 128x128 tile, BK=8, 256 threads, 8x8 micro-tile, packed f32x2 FMA.
template<int RELU, int RES>
__global__ __launch_bounds__(256, 2)
void k_gemm_nt(const float* __restrict__ A, const float* __restrict__ W,
               const float* __restrict__ bias, const float* __restrict__ res,
               float* __restrict__ C, int M, int N, int K)
{
    __shared__ float As[8][128];
    __shared__ float Bs[8][128];

    const int tid = threadIdx.x;
    const int bm  = blockIdx.y * 128;
    const int bn  = blockIdx.x * 128;

    const int lr = tid >> 1;            // 0..127
    const int lk = (tid & 1) << 2;      // 0 or 4

    const float* Ag = A + (size_t)(bm + lr) * K + lk;
    const float* Wg = W + (size_t)(bn + lr) * K + lk;

    const int tx = tid & 15;            // 0..15
    const int ty = tid >> 4;            // 0..15

    unsigned long long acc2[8][4];      // [row][jpair] packed fp32 pairs
#pragma unroll
    for (int i = 0; i < 8; i++)
#pragma unroll
        for (int j = 0; j < 4; j++) acc2[i][j] = 0ull;

    float4 ra = *(const float4*)Ag;
    float4 rw = *(const float4*)Wg;

    const int nIter = K >> 3;
    for (int it = 0; it < nIter; ++it) {
        As[lk+0][lr] = ra.x; As[lk+1][lr] = ra.y; As[lk+2][lr] = ra.z; As[lk+3][lr] = ra.w;
        Bs[lk+0][lr] = rw.x; Bs[lk+1][lr] = rw.y; Bs[lk+2][lr] = rw.z; Bs[lk+3][lr] = rw.w;
        __syncthreads();
        if (it + 1 < nIter) {
            ra = *(const float4*)(Ag + (size_t)(it+1) * 8);
            rw = *(const float4*)(Wg + (size_t)(it+1) * 8);
        }
#pragma unroll
        for (int kk = 0; kk < 8; ++kk) {
            float af[8];
            *(float4*)&af[0] = *(const float4*)&As[kk][ty*4];
            *(float4*)&af[4] = *(const float4*)&As[kk][64 + ty*4];
            float4 b0 = *(const float4*)&Bs[kk][tx*4];
            float4 b1 = *(const float4*)&Bs[kk][64 + tx*4];
            unsigned long long bp0 = pk2(b0.x, b0.y);
            unsigned long long bp1 = pk2(b0.z, b0.w);
            unsigned long long bp2 = pk2(b1.x, b1.y);
            unsigned long long bp3 = pk2(b1.z, b1.w);
#pragma unroll
            for (int i = 0; i < 8; i++) {
                unsigned long long ap = pk2(af[i], af[i]);
                acc2[i][0] = ffma2(ap, bp0, acc2[i][0]);
                acc2[i][1] = ffma2(ap, bp1, acc2[i][1]);
                acc2[i][2] = ffma2(ap, bp2, acc2[i][2]);
                acc2[i][3] = ffma2(ap, bp3, acc2[i][3]);
            }
        }
        __syncthreads();
    }

    // epilogue (vectorized, coalesced)
#pragma unroll
    for (int ih = 0; ih < 2; ih++) {
#pragma unroll
        for (int ii = 0; ii < 4; ii++) {
            int i = ih*4 + ii;
            int m = bm + ih*64 + ty*4 + ii;
            float* crow = C + (size_t)m * N;
#pragma unroll
            for (int jh = 0; jh < 2; jh++) {
                int n = bn + jh*64 + tx*4;
                float4 bv = *(const float4*)&bias[n];
                float2 p0 = upk2(acc2[i][jh*2+0]);
                float2 p1 = upk2(acc2[i][jh*2+1]);
                float4 v;
                v.x = p0.x + bv.x;
                v.y = p0.y + bv.y;
                v.z = p1.x + bv.z;
                v.w = p1.y + bv.w;
                if (RELU) {
                    v.x = fmaxf(v.x, 0.f); v.y = fmaxf(v.y, 0.f);
                    v.z = fmaxf(v.z, 0.f); v.w = fmaxf(v.w, 0.f);
                }
                if (RES) {
                    float4 rv = *(const float4*)(res + (size_t)m * N + n);
                    v.x += rv.x; v.y += rv.y; v.z += rv.z; v.w += rv.w;
                }
                *(float4*)&crow[n] = v;
            }
        }
    }
}

// ---------------- persistent bidirectional LSTM recurrence (one layer) ----------------
// grid = 128 blocks: [0,64) fwd, [64,128) bwd. Each block owns 4 hidden units
// (16 gate-rows), Whh slice cached in smem, h exchanged via L2.
// Inter-block sync: per-block flag words (NO contended atomics).
__global__ __launch_bounds__(256, 1)
void k_lstm(const float* __restrict__ xw,   // [4096][2048] (dir*1024 + gate*256 + j)
            const float* __restrict__ Whh,  // [2][1024][256] for this layer
            float* __restrict__ out)        // [4096][512], col = dir*256 + j
{
    __shared__ float Wsh[16][260];
    __shared__ float hsh[16][260];
    __shared__ float gsh[4][4][16];   // [gate][j_local][batch]
    __shared__ float csh[4][16];

    const int blk = blockIdx.x;
    const int dir = blk >> 6;
    const int bb  = blk & 63;
    const int j0  = bb * 4;
    const int tid = threadIdx.x;

    const int rl   = tid >> 4;        // 0..15 local gate-row
    const int b    = tid & 15;        // batch
    const int gate = rl >> 2;
    const int jl   = rl & 3;
    const int grow = gate * 256 + j0 + jl;   // global gate row in [0,1024)

    // load Whh slice (16 rows x 256) into smem once
    const float* Wd = Whh + (size_t)dir * 1024 * 256;
    for (int idx = tid; idx < 16 * 256; idx += 256) {
        int r = idx >> 8, k = idx & 255;
        int gg = r >> 2, jj = r & 3;
        Wsh[r][k] = Wd[(size_t)(gg * 256 + j0 + jj) * 256 + k];
    }
    if (tid < 64) csh[tid >> 4][tid & 15] = 0.f;
    __syncthreads();

    // per-thread streaming pointers (avoid 64-bit mul per step)
    const int t0 = dir ? 255 : 0;
    const long long tstride = dir ? -2048 : 2048;
    const float* xp = xw + ((size_t)(b * TQ + t0)) * 2048 + dir * 1024 + grow;
    float* op = out + ((size_t)(b * TQ + t0)) * DQ + dir * HQ + j0 + rl;  // used by rl<4
    const long long ostride = dir ? -(long long)DQ : (long long)DQ;

    for (int s = 0; s < 256; ++s) {
        // issue xw load early (overlaps with staging)
        float xv = __ldg(xp);
        xp += tstride;

        // stage h_prev into smem
        if (s == 0) {
            for (int i = tid; i < 16 * 64; i += 256) {
                int b2 = i >> 6, k4 = (i & 63) << 2;
                *(float4*)&hsh[b2][k4] = make_float4(0.f, 0.f, 0.f, 0.f);
            }
        } else {
            const float4* hp = (const float4*)&g_h[dir][(s - 1) & 1][0][0];
#pragma unroll
            for (int r = 0; r < 4; r++) {
                int i = tid + r * 256;
                float4 v = __ldcg(hp + i);            // bypass L1 (cross-block data)
                int b2 = i >> 6, k4 = (i & 63) << 2;
                *(float4*)&hsh[b2][k4] = v;
            }
        }
        __syncthreads();

        // dot product: gate[grow][b] = xw + Whh_row . h[b]  (packed f32x2 FMA)
        {
            unsigned long long s0 = 0ull, s1 = 0ull;
            const ulonglong2* wr2 = (const ulonglong2*)&Wsh[rl][0];
            const ulonglong2* hr2 = (const ulonglong2*)&hsh[b][0];
#pragma unroll
            for (int k = 0; k < 64; ++k) {
                ulonglong2 w = wr2[k];
                ulonglong2 h = hr2[k];
                s0 = ffma2(w.x, h.x, s0);
                s1 = ffma2(w.y, h.y, s1);
            }
            float2 p0 = upk2(s0), p1 = upk2(s1);
            gsh[gate][jl][b] = xv + ((p0.x + p0.y) + (p1.x + p1.y));
        }
        __syncthreads();

        // combine gates -> c, h  (64 threads: rl<4 acts as j_local)
        if (rl < 4) {
            float iv = gsh[0][rl][b];
            float fv = gsh[1][rl][b];
            float gv = gsh[2][rl][b];
            float ov = gsh[3][rl][b];
            float c  = sigf(fv) * csh[rl][b] + sigf(iv) * tanh_fast(gv);
            csh[rl][b] = c;
            float h  = sigf(ov) * tanh_fast(c);
            g_h[dir][s & 1][b][j0 + rl] = h;
            *op = h;
        }
        if (rl < 4) op += ostride;

        if (s < 255) {
            __syncthreads();                      // all h stores issued (execution order)
            if (tid == 0) {
                __threadfence();                  // cumulative: h-writes visible before flag
                *((volatile unsigned*)&g_flags[dir][bb]) = (unsigned)(s + 1);
            }
            // poll all 64 flags of this direction (distinct addresses, no atomics)
            const unsigned tgt = (unsigned)(s + 1);
            bool ok;
            do {
                ok = true;
                if (tid < 16) {
                    uint4 v = __ldcg((const uint4*)&g_flags[dir][0] + tid);
                    ok = (v.x >= tgt) & (v.y >= tgt) & (v.z >= tgt) & (v.w >= tgt);
                }
            } while (!__syncthreads_and(ok));
        }
    }
}

// ---------------- emissions: em = ho(4096x256) @ out_W(20x256)^T + out_b ----------------
__global__ void k_emout(const float* __restrict__ ho, const float* __restrict__ Wo,
                        const float* __restrict__ bo, float* __restrict__ em)
{
    __shared__ float Ws[KQ * HQ];
    for (int i = threadIdx.x; i < KQ * HQ; i += blockDim.x) Ws[i] = Wo[i];
    __syncthreads();
    int m0 = blockIdx.x * 64;
    for (int idx = threadIdx.x; idx < 64 * KQ; idx += blockDim.x) {
        int mi = idx / KQ, n = idx % KQ;
        const float* a = ho + (size_t)(m0 + mi) * HQ;
        const float* w = Ws + n * HQ;
        float s0 = 0.f, s1 = 0.f, s2 = 0.f, s3 = 0.f;
#pragma unroll
        for (int k = 0; k < HQ; k += 4) {
            float4 av = __ldg((const float4*)(a + k));
            float4 wv = *(const float4*)(w + k);
            s0 = fmaf(av.x, wv.x, s0); s1 = fmaf(av.y, wv.y, s1);
            s2 = fmaf(av.z, wv.z, s2); s3 = fmaf(av.w, wv.w, s3);
        }
        em[(size_t)(m0 + mi) * KQ + n] = bo[n] + ((s0 + s1) + (s2 + s3));
    }
}

// ---------------- Viterbi decode: one block (warp) per batch ----------------
__global__ void k_viterbi(const float* __restrict__ em, const float* __restrict__ start,
                          const float* __restrict__ endw, const float* __restrict__ trans,
                          float* __restrict__ tagout)
{
    __shared__ float sc[2][KQ];
    __shared__ float tr[KQ * KQ];
    __shared__ unsigned char hist[TQ - 1][KQ];

    const int bq = blockIdx.x;
    const int tj = threadIdx.x;
    for (int i = tj; i < KQ * KQ; i += 32) tr[i] = trans[i];
    const float* e = em + (size_t)bq * TQ * KQ;
    if (tj < KQ) sc[0][tj] = start[tj] + e[tj];
    __syncwarp();

    for (int t = 1; t < TQ; ++t) {
        if (tj < KQ) {
            const float* sp = sc[(t - 1) & 1];
            float best = -3.4e38f; int bi = 0;
#pragma unroll
            for (int i = 0; i < KQ; ++i) {
                float v = sp[i] + tr[i * KQ + tj];
                if (v > best) { best = v; bi = i; }   // first-max like jnp.argmax
            }
            sc[t & 1][tj] = best + e[(size_t)t * KQ + tj];
            hist[t - 1][tj] = (unsigned char)bi;
        }
        __syncwarp();
    }

    if (tj == 0) {
        float best = -3.4e38f; int tag = 0;
        for (int j = 0; j < KQ; ++j) {
            float v = sc[(TQ - 1) & 1][j] + endw[j];
            if (v > best) { best = v; tag = j; }
        }
        float* to = tagout + (size_t)bq * TQ;
        to[TQ - 1] = (float)tag;
        for (int t = TQ - 2; t >= 0; --t) {
            tag = hist[t][tag];
            to[t] = (float)tag;
        }
    }
}

// ---------------- launcher (graph-capturable: launches + memset only) ----------------
extern "C" void kernel_launch(void* const* d_in, const int* in_sizes, int n_in,
                              void* d_out, int out_size)
{
    const int*   x    = (const int*)  d_in[0];
    const float* emb  = (const float*)d_in[1];
    const float* Wih  = (const float*)d_in[2];   // (2,2,1024,512)
    const float* Whh  = (const float*)d_in[3];   // (2,2,1024,256)
    const float* lb   = (const float*)d_in[4];   // (2,2,1024)
    const float* fW1  = (const float*)d_in[5];   // (2,512,512)
    const float* fb1  = (const float*)d_in[6];
    const float* fW2  = (const float*)d_in[7];
    const float* fb2  = (const float*)d_in[8];
    const float* foW  = (const float*)d_in[9];   // (256,512)
    const float* fob  = (const float*)d_in[10];
    const float* oW   = (const float*)d_in[11];  // (20,256)
    const float* ob   = (const float*)d_in[12];
    const float* cs   = (const float*)d_in[13];
    const float* ce   = (const float*)d_in[14];
    const float* ct   = (const float*)d_in[15];
    float* out = (float*)d_out;

    float *p_e, *p_l0, *p_l1, *p_t, *p_f, *p_ho, *p_xw; void* p_flags;
    cudaGetSymbolAddress((void**)&p_e,  g_e);
    cudaGetSymbolAddress((void**)&p_l0, g_l0);
    cudaGetSymbolAddress((void**)&p_l1, g_l1);
    cudaGetSymbolAddress((void**)&p_t,  g_t);
    cudaGetSymbolAddress((void**)&p_f,  g_f);
    cudaGetSymbolAddress((void**)&p_ho, g_ho);
    cudaGetSymbolAddress((void**)&p_xw, g_xw);
    cudaGetSymbolAddress(&p_flags, g_flags);

    // 1. embedding
    k_embed<<<MR, 128>>>(x, emb, p_e);

    // 2. layer 0: xw GEMM (N covers both directions: 2048 rows of Wih[0])
    k_gemm_nt<0,0><<<dim3(2048/128, MR/128), 256>>>(p_e, Wih, lb, nullptr, p_xw, MR, 2048, 512);
    cudaMemsetAsync(p_flags, 0, 2 * 64 * sizeof(unsigned));
    k_lstm<<<2 * NB_DIR, 256>>>(p_xw, Whh, p_l0);

    // 3. layer 1
    k_gemm_nt<0,0><<<dim3(2048/128, MR/128), 256>>>(p_l0, Wih + (size_t)2*1024*512,
                                                    lb + 2048, nullptr, p_xw, MR, 2048, 512);
    cudaMemsetAsync(p_flags, 0, 2 * 64 * sizeof(unsigned));
    k_lstm<<<2 * NB_DIR, 256>>>(p_xw, Whh + (size_t)2*1024*256, p_l1);

    // 4. feedforward blocks (residual added in the last GEMM)
    k_gemm_nt<1,0><<<dim3(512/128, MR/128), 256>>>(p_l1, fW1, fb1, nullptr, p_t, MR, 512, 512);
    k_gemm_nt<0,0><<<dim3(512/128, MR/128), 256>>>(p_t,  fW2, fb2, nullptr, p_f, MR, 512, 512);
    k_gemm_nt<1,0><<<dim3(512/128, MR/128), 256>>>(p_f,  fW1 + 512*512, fb1 + 512, nullptr, p_t, MR, 512, 512);
    k_gemm_nt<0,1><<<dim3(512/128, MR/128), 256>>>(p_t,  fW2 + 512*512, fb2 + 512, p_l1, p_f, MR, 512, 512);

    // 5. output projections
    k_gemm_nt<0,0><<<dim3(256/128, MR/128), 256>>>(p_f, foW, fob, nullptr, p_ho, MR, 256, 512);
    k_emout<<<MR/64, 256>>>(p_ho, oW, ob, out);

    // 6. Viterbi tags appended after em (as float)
    if (out_size >= MR * KQ + MR) {
        k_viterbi<<<BQ, 32>>>(out, cs, ce, ct, out + MR * KQ);
    }
}

// round 13
// speedup vs baseline: 1.5858x; 1.5858x over previous
#include <cuda_runtime.h>
#include <math.h>

// Problem constants
#define BQ 16
#define TQ 256
#define DQ 512
#define HQ 256
#define KQ 20
#define MR (BQ*TQ)          // 4096 rows
#define NB_DIR 64           // persistent blocks per LSTM direction

// ---------------- device scratch (no runtime allocation allowed) ----------------
__device__ float g_e [MR*DQ];        // embedding out / layer-0 input
__device__ float g_l0[MR*DQ];        // layer-0 bilstm output
__device__ float g_l1[MR*DQ];        // layer-1 bilstm output (residual source)
__device__ float g_t [MR*DQ];        // ff temp (relu)
__device__ float g_f [MR*DQ];        // ff temp
__device__ float g_ho[MR*HQ];        // ffo output
__device__ float g_xw[MR*2048];      // precomputed input-gate activations (both dirs)
__device__ float g_h [2][2][BQ][HQ]; // [dir][pingpong][batch][hidden]
__device__ unsigned g_bar[2];        // per-direction barrier counters

// ---------------- fast activations (accurate to ~1e-6 rel) ----------------
__device__ __forceinline__ float sigf(float x) {
    return __fdividef(1.f, 1.f + __expf(-x));
}
__device__ __forceinline__ float tanh_fast(float x) {
    // tanh(x) = 1 - 2/(e^{2x}+1); saturates to +/-1 cleanly at overflow.
    return 1.f - __fdividef(2.f, __expf(2.f * x) + 1.f);
}

// ---------------- embedding gather ----------------
__global__ void k_embed(const int* __restrict__ x, const float* __restrict__ emb,
                        float* __restrict__ out)
{
    int row = blockIdx.x;                       // b*T + t
    int tok = x[row];
    const float4* src = (const float4*)(emb + (size_t)tok * DQ);
    float4*       dst = (float4*)(out + (size_t)row * DQ);
    for (int i = threadIdx.x; i < DQ/4; i += blockDim.x) dst[i] = src[i];
}

// ---------------- SGEMM: C[M,N] = A[M,K] * W[N,K]^T + bias (NT, fp32) ----------------
// 128x128 tile, BK=8, 256 threads, 8x8 micro-tile, float4 frags. (R2 measured-best form)
template<int RELU, int RES>
__global__ __launch_bounds__(256, 2)
void k_gemm_nt(const float* __restrict__ A, const float* __restrict__ W,
               const float* __restrict__ bias, const float* __restrict__ res,
               float* __restrict__ C, int M, int N, int K)
{
    __shared__ float As[8][128];
    __shared__ float Bs[8][128];

    const int tid = threadIdx.x;
    const int bm  = blockIdx.y * 128;
    const int bn  = blockIdx.x * 128;

    const int lr = tid >> 1;            // 0..127
    const int lk = (tid & 1) << 2;      // 0 or 4

    const float* Ag = A + (size_t)(bm + lr) * K + lk;
    const float* Wg = W + (size_t)(bn + lr) * K + lk;

    const int tx = tid & 15;            // 0..15
    const int ty = tid >> 4;            // 0..15

    float acc[8][8];
#pragma unroll
    for (int i = 0; i < 8; i++)
#pragma unroll
        for (int j = 0; j < 8; j++) acc[i][j] = 0.f;

    float4 ra = *(const float4*)Ag;
    float4 rw = *(const float4*)Wg;

    const int nIter = K >> 3;
    for (int it = 0; it < nIter; ++it) {
        As[lk+0][lr] = ra.x; As[lk+1][lr] = ra.y; As[lk+2][lr] = ra.z; As[lk+3][lr] = ra.w;
        Bs[lk+0][lr] = rw.x; Bs[lk+1][lr] = rw.y; Bs[lk+2][lr] = rw.z; Bs[lk+3][lr] = rw.w;
        __syncthreads();
        if (it + 1 < nIter) {
            ra = *(const float4*)(Ag + (size_t)(it+1) * 8);
            rw = *(const float4*)(Wg + (size_t)(it+1) * 8);
        }
#pragma unroll
        for (int kk = 0; kk < 8; ++kk) {
            float af[8], bf[8];
            *(float4*)&af[0] = *(const float4*)&As[kk][ty*4];
            *(float4*)&af[4] = *(const float4*)&As[kk][64 + ty*4];
            *(float4*)&bf[0] = *(const float4*)&Bs[kk][tx*4];
            *(float4*)&bf[4] = *(const float4*)&Bs[kk][64 + tx*4];
#pragma unroll
            for (int i = 0; i < 8; i++)
#pragma unroll
                for (int j = 0; j < 8; j++)
                    acc[i][j] = fmaf(af[i], bf[j], acc[i][j]);
        }
        __syncthreads();
    }

    // epilogue (vectorized, coalesced)
#pragma unroll
    for (int ih = 0; ih < 2; ih++) {
#pragma unroll
        for (int ii = 0; ii < 4; ii++) {
            int m = bm + ih*64 + ty*4 + ii;
            float* crow = C + (size_t)m * N;
#pragma unroll
            for (int jh = 0; jh < 2; jh++) {
                int n = bn + jh*64 + tx*4;
                float4 bv = *(const float4*)&bias[n];
                float4 v;
                v.x = acc[ih*4+ii][jh*4+0] + bv.x;
                v.y = acc[ih*4+ii][jh*4+1] + bv.y;
                v.z = acc[ih*4+ii][jh*4+2] + bv.z;
                v.w = acc[ih*4+ii][jh*4+3] + bv.w;
                if (RELU) {
                    v.x = fmaxf(v.x, 0.f); v.y = fmaxf(v.y, 0.f);
                    v.z = fmaxf(v.z, 0.f); v.w = fmaxf(v.w, 0.f);
                }
                if (RES) {
                    float4 rv = *(const float4*)(res + (size_t)m * N + n);
                    v.x += rv.x; v.y += rv.y; v.z += rv.z; v.w += rv.w;
                }
                *(float4*)&crow[n] = v;
            }
        }
    }
}

// ---------------- persistent bidirectional LSTM recurrence (one layer) ----------------
// grid = 128 blocks: [0,64) fwd, [64,128) bwd. Each block owns 4 hidden units
// (16 gate-rows). Weights live in REGISTERS (64/thread), thread = (gate,
// batch-quad, K-slice); per-step smem traffic ~80KB/CTA vs 512KB before.
// Partial dots reduced with a 15-shfl butterfly over the 16 K-slice lanes.
__global__ __launch_bounds__(256, 1)
void k_lstm(const float* __restrict__ xw,   // [4096][2048] (dir*1024 + gate*256 + j)
            const float* __restrict__ Whh,  // [2][1024][256] for this layer
            float* __restrict__ out)        // [4096][512], col = dir*256 + j
{
    __shared__ float hsh[256][20];    // h transposed: [k][b], pad to 20 (2-way max)
    __shared__ float gsh[4][4][16];   // [gate][j_local][batch]
    __shared__ float csh[4][16];

    const int blk = blockIdx.x;
    const int dir = blk >> 6;
    const int bb  = blk & 63;
    const int j0  = bb * 4;
    const int tid = threadIdx.x;

    // dot-thread decomposition: tile = (batch-quad bg, gate rowg), K-slice l16
    const int l16  = tid & 15;        // K-slice lane (k = l16 + 16*i)
    const int tile = tid >> 4;        // 0..15
    const int bg   = tile >> 2;       // batch quad 0..3
    const int rowg = tile & 3;        // gate 0..3

    // load this thread's W tile (4 j-rows x 16 k) into registers ONCE
    float w[4][16];
    {
        const float* Wd = Whh + (size_t)dir * 1024 * 256;
#pragma unroll
        for (int ri = 0; ri < 4; ri++) {
            const float* wr = Wd + (size_t)(rowg * 256 + j0 + ri) * 256 + l16;
#pragma unroll
            for (int i = 0; i < 16; i++) w[ri][i] = __ldg(wr + 16 * i);
        }
    }
    if (tid < 64) csh[tid >> 4][tid & 15] = 0.f;

    // streaming pointers
    const int t0 = dir ? 255 : 0;
    const long long tstride = dir ? -2048 : 2048;
    // dot-thread (row, batch) after reduction: row j-idx = l16>>2, batch = bg*4 + (l16&3)
    const int bD    = bg * 4 + (l16 & 3);
    const int growD = rowg * 256 + j0 + (l16 >> 2);
    const float* xp = xw + ((size_t)(bD * TQ + t0)) * 2048 + dir * 1024 + growD;
    // combine-thread output pointer (tid<64): j = tid>>4, b = tid&15
    float* op = out + ((size_t)((tid & 15) * TQ + t0)) * DQ + dir * HQ + j0 + (tid >> 4);
    const long long ostride = dir ? -(long long)DQ : (long long)DQ;

    __syncthreads();

    for (int s = 0; s < 256; ++s) {
        // issue xw load early
        float xv = __ldg(xp);
        xp += tstride;

        // stage h_prev transposed into hsh[k][b]
        if (s == 0) {
            for (int i = tid; i < 256 * 20; i += 256) ((float*)hsh)[i] = 0.f;
        } else {
            const int bS  = tid & 15;           // batch
            const int kc  = (tid >> 4) * 16;    // k-chunk base
            const float* hp = &g_h[dir][(s - 1) & 1][bS][kc];
            float4 a0 = __ldcg((const float4*)(hp + 0));
            float4 a1 = __ldcg((const float4*)(hp + 4));
            float4 a2 = __ldcg((const float4*)(hp + 8));
            float4 a3 = __ldcg((const float4*)(hp + 12));
            hsh[kc+ 0][bS] = a0.x; hsh[kc+ 1][bS] = a0.y; hsh[kc+ 2][bS] = a0.z; hsh[kc+ 3][bS] = a0.w;
            hsh[kc+ 4][bS] = a1.x; hsh[kc+ 5][bS] = a1.y; hsh[kc+ 6][bS] = a1.z; hsh[kc+ 7][bS] = a1.w;
            hsh[kc+ 8][bS] = a2.x; hsh[kc+ 9][bS] = a2.y; hsh[kc+10][bS] = a2.z; hsh[kc+11][bS] = a2.w;
            hsh[kc+12][bS] = a3.x; hsh[kc+13][bS] = a3.y; hsh[kc+14][bS] = a3.z; hsh[kc+15][bS] = a3.w;
        }
        __syncthreads();

        // partial dots: acc[ri*4+bi] = sum over this lane's 16 k of w*h
        float acc[16];
#pragma unroll
        for (int a = 0; a < 16; a++) acc[a] = 0.f;
#pragma unroll
        for (int i = 0; i < 16; i++) {
            int k = l16 + 16 * i;
            float4 h4 = *(const float4*)&hsh[k][bg * 4];
#pragma unroll
            for (int ri = 0; ri < 4; ri++) {
                acc[ri*4+0] = fmaf(w[ri][i], h4.x, acc[ri*4+0]);
                acc[ri*4+1] = fmaf(w[ri][i], h4.y, acc[ri*4+1]);
                acc[ri*4+2] = fmaf(w[ri][i], h4.z, acc[ri*4+2]);
                acc[ri*4+3] = fmaf(w[ri][i], h4.w, acc[ri*4+3]);
            }
        }
        // butterfly reduce-scatter over 16 lanes: lane l16 ends with acc index l16
#pragma unroll
        for (int off = 8; off >= 1; off >>= 1) {
            const bool hi = (l16 & off);
#pragma unroll
            for (int i = 0; i < 8; i++) {
                if (i < off) {
                    float send = hi ? acc[i] : acc[i + off];
                    float got  = __shfl_xor_sync(0xffffffffu, send, off, 16);
                    acc[i] = (hi ? acc[i + off] : acc[i]) + got;
                }
            }
        }
        // acc[0] = full dot for (gate=rowg, j_local=l16>>2, batch=bD)
        gsh[rowg][l16 >> 2][bD] = xv + acc[0];
        __syncthreads();

        // combine gates -> c, h (tid<64: j_local = tid>>4, batch = tid&15)
        if (tid < 64) {
            const int jl = tid >> 4, b = tid & 15;
            float iv = gsh[0][jl][b];
            float fv = gsh[1][jl][b];
            float gv = gsh[2][jl][b];
            float ov = gsh[3][jl][b];
            float c  = sigf(fv) * csh[jl][b] + sigf(iv) * tanh_fast(gv);
            csh[jl][b] = c;
            float h  = sigf(ov) * tanh_fast(c);
            g_h[dir][s & 1][b][j0 + jl] = h;
            *op = h;
            op += ostride;
        }

        if (s < 255) {
            __syncthreads();                      // all h stores issued
            if (tid == 0) {
                __threadfence();                  // publish h before arrive
                atomicAdd(&g_bar[dir], 1u);
                const unsigned target = (unsigned)(s + 1) * NB_DIR;
                volatile unsigned* p = &g_bar[dir];
                while (*p < target) { }
            }
            __syncthreads();
        }
    }
}

// ---------------- emissions: em = ho(4096x256) @ out_W(20x256)^T + out_b ----------------
__global__ void k_emout(const float* __restrict__ ho, const float* __restrict__ Wo,
                        const float* __restrict__ bo, float* __restrict__ em)
{
    __shared__ float Ws[KQ * HQ];
    for (int i = threadIdx.x; i < KQ * HQ; i += blockDim.x) Ws[i] = Wo[i];
    __syncthreads();
    int m0 = blockIdx.x * 64;
    for (int idx = threadIdx.x; idx < 64 * KQ; idx += blockDim.x) {
        int mi = idx / KQ, n = idx % KQ;
        const float* a = ho + (size_t)(m0 + mi) * HQ;
        const float* w = Ws + n * HQ;
        float s0 = 0.f, s1 = 0.f, s2 = 0.f, s3 = 0.f;
#pragma unroll
        for (int k = 0; k < HQ; k += 4) {
            float4 av = __ldg((const float4*)(a + k));
            float4 wv = *(const float4*)(w + k);
            s0 = fmaf(av.x, wv.x, s0); s1 = fmaf(av.y, wv.y, s1);
            s2 = fmaf(av.z, wv.z, s2); s3 = fmaf(av.w, wv.w, s3);
        }
        em[(size_t)(m0 + mi) * KQ + n] = bo[n] + ((s0 + s1) + (s2 + s3));
    }
}

// ---------------- Viterbi decode: one block (warp) per batch ----------------
__global__ void k_viterbi(const float* __restrict__ em, const float* __restrict__ start,
                          const float* __restrict__ endw, const float* __restrict__ trans,
                          float* __restrict__ tagout)
{
    __shared__ float sc[2][KQ];
    __shared__ float tr[KQ * KQ];
    __shared__ unsigned char hist[TQ - 1][KQ];

    const int bq = blockIdx.x;
    const int tj = threadIdx.x;
    for (int i = tj; i < KQ * KQ; i += 32) tr[i] = trans[i];
    const float* e = em + (size_t)bq * TQ * KQ;
    if (tj < KQ) sc[0][tj] = start[tj] + e[tj];
    __syncwarp();

    for (int t = 1; t < TQ; ++t) {
        if (tj < KQ) {
            const float* sp = sc[(t - 1) & 1];
            float best = -3.4e38f; int bi = 0;
#pragma unroll
            for (int i = 0; i < KQ; ++i) {
                float v = sp[i] + tr[i * KQ + tj];
                if (v > best) { best = v; bi = i; }   // first-max like jnp.argmax
            }
            sc[t & 1][tj] = best + e[(size_t)t * KQ + tj];
            hist[t - 1][tj] = (unsigned char)bi;
        }
        __syncwarp();
    }

    if (tj == 0) {
        float best = -3.4e38f; int tag = 0;
        for (int j = 0; j < KQ; ++j) {
            float v = sc[(TQ - 1) & 1][j] + endw[j];
            if (v > best) { best = v; tag = j; }
        }
        float* to = tagout + (size_t)bq * TQ;
        to[TQ - 1] = (float)tag;
        for (int t = TQ - 2; t >= 0; --t) {
            tag = hist[t][tag];
            to[t] = (float)tag;
        }
    }
}

// ---------------- launcher (graph-capturable: launches + memset only) ----------------
extern "C" void kernel_launch(void* const* d_in, const int* in_sizes, int n_in,
                              void* d_out, int out_size)
{
    const int*   x    = (const int*)  d_in[0];
    const float* emb  = (const float*)d_in[1];
    const float* Wih  = (const float*)d_in[2];   // (2,2,1024,512)
    const float* Whh  = (const float*)d_in[3];   // (2,2,1024,256)
    const float* lb   = (const float*)d_in[4];   // (2,2,1024)
    const float* fW1  = (const float*)d_in[5];   // (2,512,512)
    const float* fb1  = (const float*)d_in[6];
    const float* fW2  = (const float*)d_in[7];
    const float* fb2  = (const float*)d_in[8];
    const float* foW  = (const float*)d_in[9];   // (256,512)
    const float* fob  = (const float*)d_in[10];
    const float* oW   = (const float*)d_in[11];  // (20,256)
    const float* ob   = (const float*)d_in[12];
    const float* cs   = (const float*)d_in[13];
    const float* ce   = (const float*)d_in[14];
    const float* ct   = (const float*)d_in[15];
    float* out = (float*)d_out;

    float *p_e, *p_l0, *p_l1, *p_t, *p_f, *p_ho, *p_xw; void* p_bar;
    cudaGetSymbolAddress((void**)&p_e,  g_e);
    cudaGetSymbolAddress((void**)&p_l0, g_l0);
    cudaGetSymbolAddress((void**)&p_l1, g_l1);
    cudaGetSymbolAddress((void**)&p_t,  g_t);
    cudaGetSymbolAddress((void**)&p_f,  g_f);
    cudaGetSymbolAddress((void**)&p_ho, g_ho);
    cudaGetSymbolAddress((void**)&p_xw, g_xw);
    cudaGetSymbolAddress(&p_bar, g_bar);

    // 1. embedding
    k_embed<<<MR, 128>>>(x, emb, p_e);

    // 2. layer 0: xw GEMM (N covers both directions: 2048 rows of Wih[0])
    k_gemm_nt<0,0><<<dim3(2048/128, MR/128), 256>>>(p_e, Wih, lb, nullptr, p_xw, MR, 2048, 512);
    cudaMemsetAsync(p_bar, 0, 2 * sizeof(unsigned));
    k_lstm<<<2 * NB_DIR, 256>>>(p_xw, Whh, p_l0);

    // 3. layer 1
    k_gemm_nt<0,0><<<dim3(2048/128, MR/128), 256>>>(p_l0, Wih + (size_t)2*1024*512,
                                                    lb + 2048, nullptr, p_xw, MR, 2048, 512);
    cudaMemsetAsync(p_bar, 0, 2 * sizeof(unsigned));
    k_lstm<<<2 * NB_DIR, 256>>>(p_xw, Whh + (size_t)2*1024*256, p_l1);

    // 4. feedforward blocks (residual added in the last GEMM)
    k_gemm_nt<1,0><<<dim3(512/128, MR/128), 256>>>(p_l1, fW1, fb1, nullptr, p_t, MR, 512, 512);
    k_gemm_nt<0,0><<<dim3(512/128, MR/128), 256>>>(p_t,  fW2, fb2, nullptr, p_f, MR, 512, 512);
    k_gemm_nt<1,0><<<dim3(512/128, MR/128), 256>>>(p_f,  fW1 + 512*512, fb1 + 512, nullptr, p_t, MR, 512, 512);
    k_gemm_nt<0,1><<<dim3(512/128, MR/128), 256>>>(p_t,  fW2 + 512*512, fb2 + 512, p_l1, p_f, MR, 512, 512);

    // 5. output projections
    k_gemm_nt<0,0><<<dim3(256/128, MR/128), 256>>>(p_f, foW, fob, nullptr, p_ho, MR, 256, 512);
    k_emout<<<MR/64, 256>>>(p_ho, oW, ob, out);

    // 6. Viterbi tags appended after em (as float)
    if (out_size >= MR * KQ + MR) {
        k_viterbi<<<BQ, 32>>>(out, cs, ce, ct, out + MR * KQ);
    }
}